// round 1
// baseline (speedup 1.0000x reference)
#include <cuda_runtime.h>
#include <math.h>

// ---------------- problem constants ----------------
#define BATCH   16
#define CIN     256
#define IMGH    64
#define IMGW    64
#define NPIX    4096          // 64*64
#define HEADS   4
#define DK      16
#define DV      64
#define RKS     7
#define TAPS    49            // 7*7
#define PADR    3

// ---------------- device scratch (globals: allowed) ----------------
__device__ float g_q[BATCH * 64 * NPIX];   // raw q projections [b][ch=h*16+k][p]
__device__ float g_k[BATCH * 16 * NPIX];   // raw k projections [b][k][p]
__device__ float g_v[BATCH * 64 * NPIX];   // raw v projections [b][v][p]
__device__ float g_sq[64], g_bq[64];       // BN fold for q: y = x*s + b
__device__ float g_sv[64], g_bv[64];       // BN fold for v
__device__ float g_lamc[BATCH * 16 * 64];  // lambda_c [b][k][v]

// ======================================================================
// K1: fused projection GEMM. Per batch: Y[144,4096] = W[144,256] * X[256,4096]
// rows 0..63 -> q, 64..79 -> k, 80..143 -> v (raw, pre-BN)
// block tile: 144 x 128, threads 256 as 16x16, thread tile 9x8
// ======================================================================
__global__ __launch_bounds__(256)
void k_proj(const float* __restrict__ x,
            const float* __restrict__ Wq,
            const float* __restrict__ Wk,
            const float* __restrict__ Wv) {
    __shared__ float Xs[16][128];
    __shared__ float Ws[144][17];

    const int b   = blockIdx.y;
    const int p0  = blockIdx.x * 128;
    const int tid = threadIdx.x;
    const int ty  = tid >> 4;    // 0..15 : output-row group
    const int tx  = tid & 15;    // 0..15 : pixel group

    const float* xb = x + (size_t)b * CIN * NPIX;

    float acc[9][8];
#pragma unroll
    for (int i = 0; i < 9; ++i)
#pragma unroll
        for (int j = 0; j < 8; ++j) acc[i][j] = 0.f;

    for (int c0 = 0; c0 < CIN; c0 += 16) {
        // load X chunk [16][128]
#pragma unroll
        for (int r = 0; r < 8; ++r) {
            int idx = tid + r * 256;          // 0..2047
            int cc  = idx >> 7;
            int pp  = idx & 127;
            Xs[cc][pp] = xb[(size_t)(c0 + cc) * NPIX + p0 + pp];
        }
        // load W chunk [144][16]
#pragma unroll
        for (int r = 0; r < 9; ++r) {
            int idx = tid + r * 256;          // 0..2303
            int o   = idx >> 4;
            int cc  = idx & 15;
            float w;
            if (o < 64)       w = Wq[o * CIN + c0 + cc];
            else if (o < 80)  w = Wk[(o - 64) * CIN + c0 + cc];
            else              w = Wv[(o - 80) * CIN + c0 + cc];
            Ws[o][cc] = w;
        }
        __syncthreads();

#pragma unroll
        for (int cc = 0; cc < 16; ++cc) {
            float a[9], bb[8];
#pragma unroll
            for (int i = 0; i < 9; ++i) a[i] = Ws[ty + 16 * i][cc];
#pragma unroll
            for (int j = 0; j < 8; ++j) bb[j] = Xs[cc][tx + 16 * j];
#pragma unroll
            for (int i = 0; i < 9; ++i)
#pragma unroll
                for (int j = 0; j < 8; ++j) acc[i][j] += a[i] * bb[j];
        }
        __syncthreads();
    }

    // scatter-store to q/k/v buffers (coalesced in pixels)
#pragma unroll
    for (int i = 0; i < 9; ++i) {
        int o = ty + 16 * i;
        float* dst;
        if (o < 64)      dst = g_q + ((size_t)b * 64 + o) * NPIX;
        else if (o < 80) dst = g_k + ((size_t)b * 16 + (o - 64)) * NPIX;
        else             dst = g_v + ((size_t)b * 64 + (o - 80)) * NPIX;
#pragma unroll
        for (int j = 0; j < 8; ++j) dst[p0 + tx + 16 * j] = acc[i][j];
    }
}

// ======================================================================
// K2: BN statistics -> folded scale/bias. 128 blocks (64 q-ch + 64 v-ch).
// mean/var over all batches and pixels per channel (65536 elems). Deterministic.
// ======================================================================
__global__ __launch_bounds__(256)
void k_bnstats(const float* __restrict__ gamma_q, const float* __restrict__ beta_q,
               const float* __restrict__ gamma_v, const float* __restrict__ beta_v) {
    const int ch  = blockIdx.x;   // 0..127
    const int tid = threadIdx.x;

    const float* src;
    float gamma, beta;
    float *sdst, *bdst;
    if (ch < 64) {
        src = g_q + (size_t)ch * NPIX;
        gamma = gamma_q[ch]; beta = beta_q[ch];
        sdst = &g_sq[ch]; bdst = &g_bq[ch];
    } else {
        int c = ch - 64;
        src = g_v + (size_t)c * NPIX;
        gamma = gamma_v[c]; beta = beta_v[c];
        sdst = &g_sv[c]; bdst = &g_bv[c];
    }

    float s = 0.f, s2 = 0.f;
    for (int b = 0; b < BATCH; ++b) {
        const float* p = src + (size_t)b * 64 * NPIX;
        for (int i = tid; i < NPIX; i += 256) {
            float v = p[i];
            s  += v;
            s2 += v * v;
        }
    }
    __shared__ float ss[256], ss2[256];
    ss[tid] = s; ss2[tid] = s2;
    __syncthreads();
    for (int st = 128; st > 0; st >>= 1) {
        if (tid < st) { ss[tid] += ss[tid + st]; ss2[tid] += ss2[tid + st]; }
        __syncthreads();
    }
    if (tid == 0) {
        const float inv_n = 1.0f / 65536.0f;
        float mean = ss[0] * inv_n;
        float var  = ss2[0] * inv_n - mean * mean;
        float sc   = gamma * rsqrtf(var + 1e-5f);
        *sdst = sc;
        *bdst = beta - mean * sc;
    }
}

// ======================================================================
// K3: softmax over k row + lambda_c, fused. One block per (b, k) = 256 blocks.
// lam_c[k,v] = scale_v[v] * (sum_m e^{k_m - M} v_raw[v,m]) / Z + bias_v[v]
// ======================================================================
__global__ __launch_bounds__(256)
void k_lamc() {
    const int bk  = blockIdx.x;
    const int b   = bk >> 4;
    const int kc  = bk & 15;
    const int tid = threadIdx.x;
    const int lane = tid & 31, wrp = tid >> 5;

    const float* krow = g_k + ((size_t)b * 16 + kc) * NPIX;
    const float* vb   = g_v + (size_t)b * 64 * NPIX;

    __shared__ float red[256];

    // pass 1: row max
    float m = -1e30f;
    for (int i = tid; i < NPIX; i += 256) m = fmaxf(m, krow[i]);
    red[tid] = m;
    __syncthreads();
    for (int st = 128; st > 0; st >>= 1) {
        if (tid < st) red[tid] = fmaxf(red[tid], red[tid + st]);
        __syncthreads();
    }
    m = red[0];
    __syncthreads();

    // pass 2: weighted sums
    float acc[64];
#pragma unroll
    for (int v = 0; v < 64; ++v) acc[v] = 0.f;
    float z = 0.f;

    for (int i = tid; i < NPIX; i += 256) {
        float w = expf(krow[i] - m);
        z += w;
#pragma unroll
        for (int v = 0; v < 64; ++v) acc[v] += w * vb[(size_t)v * NPIX + i];
    }

    // reduce z
    red[tid] = z;
    __syncthreads();
    for (int st = 128; st > 0; st >>= 1) {
        if (tid < st) red[tid] += red[tid + st];
        __syncthreads();
    }
    z = red[0];
    __syncthreads();
    const float invz = 1.0f / z;

    // reduce acc[64]: warp shuffle then 8 partials
    __shared__ float part[64][8];
#pragma unroll
    for (int v = 0; v < 64; ++v) {
        float xv = acc[v];
#pragma unroll
        for (int o = 16; o > 0; o >>= 1) xv += __shfl_down_sync(0xffffffffu, xv, o);
        if (lane == 0) part[v][wrp] = xv;
    }
    __syncthreads();
    if (tid < 64) {
        float sum = 0.f;
#pragma unroll
        for (int i = 0; i < 8; ++i) sum += part[tid][i];
        g_lamc[((size_t)b * 16 + kc) * 64 + tid] = g_sv[tid] * sum * invz + g_bv[tid];
    }
}

// ======================================================================
// K5: final fused output.
//   s[h,t,p]   = sum_k q_bn[h,k,p] * R[k,t]                (in-smem)
//   out[h,v,p] = sum_k q_bn[h,k,p]*lam_c[k,v]
//              + sum_t s[h,t,p] * v_bn[v, p+off_t]         (49 taps, zero-pad)
// block = 8x8 pixel tile; 256 threads = 64 pixels x 4 v-groups (16 v each).
// ======================================================================
#define VHPITCH 68   // padded channel pitch for v halo rows

__global__ __launch_bounds__(256)
void k_final(const float* __restrict__ R, float* __restrict__ out) {
    extern __shared__ float sm[];
    float* q_sm    = sm;                     // [64 ch][64 pix]          4096
    float* s_sm    = q_sm + 4096;            // [(h*49+t)][64 pix]      12544
    float* vh_sm   = s_sm + 12544;           // [196 hpix][VHPITCH]     13328
    float* lamc_sm = vh_sm + 196 * VHPITCH;  // [16 k][64 v]             1024
    float* R_sm    = lamc_sm + 1024;         // [16 k][49 t]              784

    const int b   = blockIdx.z;
    const int tx0 = blockIdx.x * 8;
    const int ty0 = blockIdx.y * 8;
    const int tid = threadIdx.x;

    // ---- loads ----
    for (int i = tid; i < 784; i += 256)  R_sm[i]    = R[i];
    for (int i = tid; i < 1024; i += 256) lamc_sm[i] = g_lamc[(size_t)b * 1024 + i];

    {   // q tile with BN, [ch][pix]
        const float* qb = g_q + (size_t)b * 64 * NPIX;
        for (int idx = tid; idx < 4096; idx += 256) {
            int ch = idx >> 6, lp = idx & 63;
            int ly = lp >> 3,  lx = lp & 7;
            float v = qb[(size_t)ch * NPIX + (ty0 + ly) * IMGW + tx0 + lx];
            q_sm[ch * 64 + lp] = v * g_sq[ch] + g_bq[ch];
        }
    }
    {   // v halo 14x14 with BN + zero pad, [hpix][ch] (padded pitch)
        const float* vb = g_v + (size_t)b * 64 * NPIX;
        for (int idx = tid; idx < 196 * 64; idx += 256) {
            int ch = idx / 196, hp = idx - ch * 196;
            int hy = hp / 14,   hx = hp - hy * 14;
            int gy = ty0 + hy - PADR, gx = tx0 + hx - PADR;
            float v = 0.f;
            if (gy >= 0 && gy < IMGH && gx >= 0 && gx < IMGW)
                v = vb[(size_t)ch * NPIX + gy * IMGW + gx] * g_sv[ch] + g_bv[ch];
            vh_sm[hp * VHPITCH + ch] = v;
        }
    }
    __syncthreads();

    const int vg  = tid >> 6;   // v-group 0..3 (16 channels each); also used as h for s-phase
    const int pix = tid & 63;

    // ---- s phase: each thread computes s[h=vg, t, pix] ----
    {
        float qk[16];
#pragma unroll
        for (int kk = 0; kk < 16; ++kk) qk[kk] = q_sm[(vg * 16 + kk) * 64 + pix];
#pragma unroll
        for (int t = 0; t < TAPS; ++t) {
            float s = 0.f;
#pragma unroll
            for (int kk = 0; kk < 16; ++kk) s += qk[kk] * R_sm[kk * TAPS + t];
            s_sm[(vg * TAPS + t) * 64 + pix] = s;
        }
    }
    __syncthreads();

    // ---- accumulate out[h=0..3][v = vg*16 .. +15] for this pixel ----
    float acc[4][16];
#pragma unroll
    for (int h = 0; h < 4; ++h)
#pragma unroll
        for (int vi = 0; vi < 16; ++vi) acc[h][vi] = 0.f;

    // Yc term
#pragma unroll
    for (int kk = 0; kk < 16; ++kk) {
        float q0 = q_sm[(0 * 16 + kk) * 64 + pix];
        float q1 = q_sm[(1 * 16 + kk) * 64 + pix];
        float q2 = q_sm[(2 * 16 + kk) * 64 + pix];
        float q3 = q_sm[(3 * 16 + kk) * 64 + pix];
        const float* lrow = lamc_sm + kk * 64 + vg * 16;
#pragma unroll
        for (int vi = 0; vi < 16; ++vi) {
            float lv = lrow[vi];
            acc[0][vi] += q0 * lv;
            acc[1][vi] += q1 * lv;
            acc[2][vi] += q2 * lv;
            acc[3][vi] += q3 * lv;
        }
    }

    // Yp term: 49 taps
    const int py = pix >> 3, px = pix & 7;
#pragma unroll
    for (int dy = 0; dy < RKS; ++dy) {
#pragma unroll
        for (int dx = 0; dx < RKS; ++dx) {
            const int t  = dy * RKS + dx;
            const int hp = (py + dy) * 14 + (px + dx);
            const float4* vp = (const float4*)(vh_sm + hp * VHPITCH + vg * 16);
            float4 v0 = vp[0], v1 = vp[1], v2 = vp[2], v3 = vp[3];
            float vv[16] = {v0.x, v0.y, v0.z, v0.w,
                            v1.x, v1.y, v1.z, v1.w,
                            v2.x, v2.y, v2.z, v2.w,
                            v3.x, v3.y, v3.z, v3.w};
            float sh0 = s_sm[(0 * TAPS + t) * 64 + pix];
            float sh1 = s_sm[(1 * TAPS + t) * 64 + pix];
            float sh2 = s_sm[(2 * TAPS + t) * 64 + pix];
            float sh3 = s_sm[(3 * TAPS + t) * 64 + pix];
#pragma unroll
            for (int vi = 0; vi < 16; ++vi) {
                acc[0][vi] += sh0 * vv[vi];
                acc[1][vi] += sh1 * vv[vi];
                acc[2][vi] += sh2 * vv[vi];
                acc[3][vi] += sh3 * vv[vi];
            }
        }
    }

    // ---- store: out channel = h*64 + v ----
    const size_t ob = (size_t)b * 256 * NPIX;
    const int gp = (ty0 + py) * IMGW + tx0 + px;
#pragma unroll
    for (int h = 0; h < 4; ++h)
#pragma unroll
        for (int vi = 0; vi < 16; ++vi)
            out[ob + (size_t)(h * 64 + vg * 16 + vi) * NPIX + gp] = acc[h][vi];
}

// ======================================================================
extern "C" void kernel_launch(void* const* d_in, const int* in_sizes, int n_in,
                              void* d_out, int out_size) {
    const float* x       = (const float*)d_in[0];
    const float* Wq      = (const float*)d_in[1];
    const float* Wk      = (const float*)d_in[2];
    const float* Wv      = (const float*)d_in[3];
    const float* gamma_q = (const float*)d_in[4];
    const float* beta_q  = (const float*)d_in[5];
    const float* gamma_v = (const float*)d_in[6];
    const float* beta_v  = (const float*)d_in[7];
    const float* R       = (const float*)d_in[8];
    float* out = (float*)d_out;

    // K5 needs >48KB dynamic smem
    const int smemK5 = (4096 + 12544 + 196 * VHPITCH + 1024 + 784) * (int)sizeof(float);
    cudaFuncSetAttribute(k_final, cudaFuncAttributeMaxDynamicSharedMemorySize, smemK5);

    k_proj<<<dim3(NPIX / 128, BATCH), 256>>>(x, Wq, Wk, Wv);
    k_bnstats<<<128, 256>>>(gamma_q, beta_q, gamma_v, beta_v);
    k_lamc<<<BATCH * 16, 256>>>();
    k_final<<<dim3(8, 8, BATCH), 256, smemK5>>>(R, out);
}

// round 2
// speedup vs baseline: 1.2343x; 1.2343x over previous
#include <cuda_runtime.h>
#include <math.h>

// ---------------- problem constants ----------------
#define BATCH   16
#define CIN     256
#define IMGH    64
#define IMGW    64
#define NPIX    4096          // 64*64
#define HEADS   4
#define DK      16
#define DV      64
#define RKS     7
#define TAPS    49            // 7*7
#define PADR    3

// ---------------- device scratch (globals: allowed) ----------------
__device__ float g_q[BATCH * 64 * NPIX];   // raw q projections [b][ch=h*16+k][p]
__device__ float g_k[BATCH * 16 * NPIX];   // raw k projections [b][k][p]
__device__ float g_v[BATCH * 64 * NPIX];   // raw v projections [b][v][p]
__device__ float g_sq[64], g_bq[64];       // BN fold for q: y = x*s + b
__device__ float g_sv[64], g_bv[64];       // BN fold for v
__device__ float g_lamc[BATCH * 16 * 64];  // lambda_c [b][k][v]

// ======================================================================
// K1: fused projection GEMM. Per batch: Y[144,4096] = W[144,256] * X[256,4096]
// rows 0..63 -> q, 64..79 -> k, 80..143 -> v (raw, pre-BN)
// block tile: 144 x 128, threads 256 as 16x16, thread tile 9x8
// ======================================================================
__global__ __launch_bounds__(256)
void k_proj(const float* __restrict__ x,
            const float* __restrict__ Wq,
            const float* __restrict__ Wk,
            const float* __restrict__ Wv) {
    __shared__ float Xs[16][128];
    __shared__ float Ws[144][17];

    const int b   = blockIdx.y;
    const int p0  = blockIdx.x * 128;
    const int tid = threadIdx.x;
    const int ty  = tid >> 4;    // 0..15 : output-row group
    const int tx  = tid & 15;    // 0..15 : pixel group

    const float* xb = x + (size_t)b * CIN * NPIX;

    float acc[9][8];
#pragma unroll
    for (int i = 0; i < 9; ++i)
#pragma unroll
        for (int j = 0; j < 8; ++j) acc[i][j] = 0.f;

    for (int c0 = 0; c0 < CIN; c0 += 16) {
        // load X chunk [16][128]
#pragma unroll
        for (int r = 0; r < 8; ++r) {
            int idx = tid + r * 256;          // 0..2047
            int cc  = idx >> 7;
            int pp  = idx & 127;
            Xs[cc][pp] = xb[(size_t)(c0 + cc) * NPIX + p0 + pp];
        }
        // load W chunk [144][16]
#pragma unroll
        for (int r = 0; r < 9; ++r) {
            int idx = tid + r * 256;          // 0..2303
            int o   = idx >> 4;
            int cc  = idx & 15;
            float w;
            if (o < 64)       w = Wq[o * CIN + c0 + cc];
            else if (o < 80)  w = Wk[(o - 64) * CIN + c0 + cc];
            else              w = Wv[(o - 80) * CIN + c0 + cc];
            Ws[o][cc] = w;
        }
        __syncthreads();

#pragma unroll
        for (int cc = 0; cc < 16; ++cc) {
            float a[9], bb[8];
#pragma unroll
            for (int i = 0; i < 9; ++i) a[i] = Ws[ty + 16 * i][cc];
#pragma unroll
            for (int j = 0; j < 8; ++j) bb[j] = Xs[cc][tx + 16 * j];
#pragma unroll
            for (int i = 0; i < 9; ++i)
#pragma unroll
                for (int j = 0; j < 8; ++j) acc[i][j] += a[i] * bb[j];
        }
        __syncthreads();
    }

    // scatter-store to q/k/v buffers (coalesced in pixels)
#pragma unroll
    for (int i = 0; i < 9; ++i) {
        int o = ty + 16 * i;
        float* dst;
        if (o < 64)      dst = g_q + ((size_t)b * 64 + o) * NPIX;
        else if (o < 80) dst = g_k + ((size_t)b * 16 + (o - 64)) * NPIX;
        else             dst = g_v + ((size_t)b * 64 + (o - 80)) * NPIX;
#pragma unroll
        for (int j = 0; j < 8; ++j) dst[p0 + tx + 16 * j] = acc[i][j];
    }
}

// ======================================================================
// K2: BN statistics -> folded scale/bias. 128 blocks (64 q-ch + 64 v-ch).
// ======================================================================
__global__ __launch_bounds__(256)
void k_bnstats(const float* __restrict__ gamma_q, const float* __restrict__ beta_q,
               const float* __restrict__ gamma_v, const float* __restrict__ beta_v) {
    const int ch  = blockIdx.x;   // 0..127
    const int tid = threadIdx.x;

    const float* src;
    float gamma, beta;
    float *sdst, *bdst;
    if (ch < 64) {
        src = g_q + (size_t)ch * NPIX;
        gamma = gamma_q[ch]; beta = beta_q[ch];
        sdst = &g_sq[ch]; bdst = &g_bq[ch];
    } else {
        int c = ch - 64;
        src = g_v + (size_t)c * NPIX;
        gamma = gamma_v[c]; beta = beta_v[c];
        sdst = &g_sv[c]; bdst = &g_bv[c];
    }

    float s = 0.f, s2 = 0.f;
    for (int b = 0; b < BATCH; ++b) {
        const float* p = src + (size_t)b * 64 * NPIX;
        for (int i = tid; i < NPIX; i += 256) {
            float v = p[i];
            s  += v;
            s2 += v * v;
        }
    }
    __shared__ float ss[256], ss2[256];
    ss[tid] = s; ss2[tid] = s2;
    __syncthreads();
    for (int st = 128; st > 0; st >>= 1) {
        if (tid < st) { ss[tid] += ss[tid + st]; ss2[tid] += ss2[tid + st]; }
        __syncthreads();
    }
    if (tid == 0) {
        const float inv_n = 1.0f / 65536.0f;
        float mean = ss[0] * inv_n;
        float var  = ss2[0] * inv_n - mean * mean;
        float sc   = gamma * rsqrtf(var + 1e-5f);
        *sdst = sc;
        *bdst = beta - mean * sc;
    }
}

// ======================================================================
// K3: softmax over k row + lambda_c, fused. One block per (b, k) = 256 blocks.
// ======================================================================
__global__ __launch_bounds__(256)
void k_lamc() {
    const int bk  = blockIdx.x;
    const int b   = bk >> 4;
    const int kc  = bk & 15;
    const int tid = threadIdx.x;
    const int lane = tid & 31, wrp = tid >> 5;

    const float* krow = g_k + ((size_t)b * 16 + kc) * NPIX;
    const float* vb   = g_v + (size_t)b * 64 * NPIX;

    __shared__ float red[256];

    // pass 1: row max
    float m = -1e30f;
    for (int i = tid; i < NPIX; i += 256) m = fmaxf(m, krow[i]);
    red[tid] = m;
    __syncthreads();
    for (int st = 128; st > 0; st >>= 1) {
        if (tid < st) red[tid] = fmaxf(red[tid], red[tid + st]);
        __syncthreads();
    }
    m = red[0];
    __syncthreads();

    // pass 2: weighted sums
    float acc[64];
#pragma unroll
    for (int v = 0; v < 64; ++v) acc[v] = 0.f;
    float z = 0.f;

    for (int i = tid; i < NPIX; i += 256) {
        float w = expf(krow[i] - m);
        z += w;
#pragma unroll
        for (int v = 0; v < 64; ++v) acc[v] += w * vb[(size_t)v * NPIX + i];
    }

    // reduce z
    red[tid] = z;
    __syncthreads();
    for (int st = 128; st > 0; st >>= 1) {
        if (tid < st) red[tid] += red[tid + st];
        __syncthreads();
    }
    z = red[0];
    __syncthreads();
    const float invz = 1.0f / z;

    __shared__ float part[64][8];
#pragma unroll
    for (int v = 0; v < 64; ++v) {
        float xv = acc[v];
#pragma unroll
        for (int o = 16; o > 0; o >>= 1) xv += __shfl_down_sync(0xffffffffu, xv, o);
        if (lane == 0) part[v][wrp] = xv;
    }
    __syncthreads();
    if (tid < 64) {
        float sum = 0.f;
#pragma unroll
        for (int i = 0; i < 8; ++i) sum += part[tid][i];
        g_lamc[((size_t)b * 16 + kc) * 64 + tid] = g_sv[tid] * sum * invz + g_bv[tid];
    }
}

// ======================================================================
// K5: final fused output (restructured for 2 CTAs/SM).
//   Yc: out[h,v,p] += sum_k q_bn[h,k,p]*lam_c[k,v]
//   Yp: loop dy = 0..6:
//         s[h,tt,p] = sum_k q_bn[h,k,p] * R[k, dy*7+tt]   (7 taps only)
//         out[h,v,p] += sum_tt s[h,tt,p] * v_bn[v, p+off(dy,tt)]
// s buffer shrinks 49 taps -> 7 taps: smem 127KB -> 84KB -> occupancy 2x.
// block = 8x8 pixel tile; 256 threads = 64 pixels x 4 v-groups (16 v each).
// ======================================================================
#define VHPITCH 68   // padded channel pitch for v halo rows

__global__ __launch_bounds__(256, 2)
void k_final(const float* __restrict__ R, float* __restrict__ out) {
    extern __shared__ float sm[];
    float* q_sm    = sm;                     // [64 ch][64 pix]          4096
    float* vh_sm   = q_sm + 4096;            // [196 hpix][VHPITCH]     13328
    float* s_sm    = vh_sm + 196 * VHPITCH;  // [4h][7 tt][64 pix]       1792
    float* lamc_sm = s_sm + 1792;            // [16 k][64 v]             1024
    float* R_sm    = lamc_sm + 1024;         // [16 k][49 t]              784

    const int b   = blockIdx.z;
    const int tx0 = blockIdx.x * 8;
    const int ty0 = blockIdx.y * 8;
    const int tid = threadIdx.x;

    // ---- loads ----
    for (int i = tid; i < 784; i += 256)  R_sm[i]    = R[i];
    for (int i = tid; i < 1024; i += 256) lamc_sm[i] = g_lamc[(size_t)b * 1024 + i];

    {   // q tile with BN, [ch][pix]
        const float* qb = g_q + (size_t)b * 64 * NPIX;
        for (int idx = tid; idx < 4096; idx += 256) {
            int ch = idx >> 6, lp = idx & 63;
            int ly = lp >> 3,  lx = lp & 7;
            float v = qb[(size_t)ch * NPIX + (ty0 + ly) * IMGW + tx0 + lx];
            q_sm[ch * 64 + lp] = v * g_sq[ch] + g_bq[ch];
        }
    }
    {   // v halo 14x14 with BN + zero pad, [hpix][ch] (padded pitch)
        const float* vb = g_v + (size_t)b * 64 * NPIX;
        for (int idx = tid; idx < 196 * 64; idx += 256) {
            int ch = idx / 196, hp = idx - ch * 196;
            int hy = hp / 14,   hx = hp - hy * 14;
            int gy = ty0 + hy - PADR, gx = tx0 + hx - PADR;
            float v = 0.f;
            if (gy >= 0 && gy < IMGH && gx >= 0 && gx < IMGW)
                v = vb[(size_t)ch * NPIX + gy * IMGW + gx] * g_sv[ch] + g_bv[ch];
            vh_sm[hp * VHPITCH + ch] = v;
        }
    }
    __syncthreads();

    const int vg  = tid >> 6;   // v-group 0..3 (16 channels each); also h for s-phase
    const int pix = tid & 63;
    const int py  = pix >> 3, px = pix & 7;

    float acc[4][16];
#pragma unroll
    for (int h = 0; h < 4; ++h)
#pragma unroll
        for (int vi = 0; vi < 16; ++vi) acc[h][vi] = 0.f;

    // ---- Yc term ----
#pragma unroll
    for (int kk = 0; kk < 16; ++kk) {
        float q0 = q_sm[(0 * 16 + kk) * 64 + pix];
        float q1 = q_sm[(1 * 16 + kk) * 64 + pix];
        float q2 = q_sm[(2 * 16 + kk) * 64 + pix];
        float q3 = q_sm[(3 * 16 + kk) * 64 + pix];
        const float* lrow = lamc_sm + kk * 64 + vg * 16;
#pragma unroll
        for (int vi = 0; vi < 16; ++vi) {
            float lv = lrow[vi];
            acc[0][vi] += q0 * lv;
            acc[1][vi] += q1 * lv;
            acc[2][vi] += q2 * lv;
            acc[3][vi] += q3 * lv;
        }
    }

    // ---- Yp term: dy row-groups of the 7x7 stencil ----
    for (int dy = 0; dy < RKS; ++dy) {
        __syncthreads();   // protect s_sm writers from previous-iteration readers
        // s phase: thread computes s[h=vg][tt=0..6][pix]
        {
            float qk[16];
#pragma unroll
            for (int kk = 0; kk < 16; ++kk) qk[kk] = q_sm[(vg * 16 + kk) * 64 + pix];
#pragma unroll
            for (int tt = 0; tt < RKS; ++tt) {
                float s = 0.f;
#pragma unroll
                for (int kk = 0; kk < 16; ++kk) s += qk[kk] * R_sm[kk * TAPS + dy * RKS + tt];
                s_sm[(vg * RKS + tt) * 64 + pix] = s;
            }
        }
        __syncthreads();

#pragma unroll
        for (int dx = 0; dx < RKS; ++dx) {
            const int hp = (py + dy) * 14 + (px + dx);
            const float4* vp = (const float4*)(vh_sm + hp * VHPITCH + vg * 16);
            float4 v0 = vp[0], v1 = vp[1], v2 = vp[2], v3 = vp[3];
            float vv[16] = {v0.x, v0.y, v0.z, v0.w,
                            v1.x, v1.y, v1.z, v1.w,
                            v2.x, v2.y, v2.z, v2.w,
                            v3.x, v3.y, v3.z, v3.w};
            float sh0 = s_sm[(0 * RKS + dx) * 64 + pix];
            float sh1 = s_sm[(1 * RKS + dx) * 64 + pix];
            float sh2 = s_sm[(2 * RKS + dx) * 64 + pix];
            float sh3 = s_sm[(3 * RKS + dx) * 64 + pix];
#pragma unroll
            for (int vi = 0; vi < 16; ++vi) {
                acc[0][vi] += sh0 * vv[vi];
                acc[1][vi] += sh1 * vv[vi];
                acc[2][vi] += sh2 * vv[vi];
                acc[3][vi] += sh3 * vv[vi];
            }
        }
    }

    // ---- store: out channel = h*64 + v ----
    const size_t ob = (size_t)b * 256 * NPIX;
    const int gp = (ty0 + py) * IMGW + tx0 + px;
#pragma unroll
    for (int h = 0; h < 4; ++h)
#pragma unroll
        for (int vi = 0; vi < 16; ++vi)
            out[ob + (size_t)(h * 64 + vg * 16 + vi) * NPIX + gp] = acc[h][vi];
}

// ======================================================================
extern "C" void kernel_launch(void* const* d_in, const int* in_sizes, int n_in,
                              void* d_out, int out_size) {
    const float* x       = (const float*)d_in[0];
    const float* Wq      = (const float*)d_in[1];
    const float* Wk      = (const float*)d_in[2];
    const float* Wv      = (const float*)d_in[3];
    const float* gamma_q = (const float*)d_in[4];
    const float* beta_q  = (const float*)d_in[5];
    const float* gamma_v = (const float*)d_in[6];
    const float* beta_v  = (const float*)d_in[7];
    const float* R       = (const float*)d_in[8];
    float* out = (float*)d_out;

    const int smemK5 = (4096 + 196 * VHPITCH + 1792 + 1024 + 784) * (int)sizeof(float);
    cudaFuncSetAttribute(k_final, cudaFuncAttributeMaxDynamicSharedMemorySize, smemK5);

    k_proj<<<dim3(NPIX / 128, BATCH), 256>>>(x, Wq, Wk, Wv);
    k_bnstats<<<128, 256>>>(gamma_q, beta_q, gamma_v, beta_v);
    k_lamc<<<BATCH * 16, 256>>>();
    k_final<<<dim3(8, 8, BATCH), 256, smemK5>>>(R, out);
}